// round 3
// baseline (speedup 1.0000x reference)
#include <cuda_runtime.h>
#include <cuda_bf16.h>
#include <cstdint>

// Problem constants
#define BB   2
#define CC   128
#define HH   48
#define NTOK 2304          // 48*48
#define NHEADS 8
#define CHH  16            // C / heads
#define KTOP 1843          // int(2304 * 0.8)

typedef unsigned long long ull;

// ---------------- scratch (no allocations allowed) ----------------
__device__ float g_q[BB*CC*NTOK];                      // fp32 q (pre-norm)
__device__ __nv_bfloat16 g_kT[BB*NHEADS*NTOK*CHH];     // normalized K, [bh][n][ch]
__device__ __nv_bfloat16 g_v16[BB*CC*NTOK];            // v bf16, [b*C+c][n]
__device__ float g_attn[BB*CC*NTOK];                   // attention output fp32

// ---------------- packed f32x2 helpers (outconv) ----------------
__device__ __forceinline__ ull pk2(float lo, float hi) {
    ull r; asm("mov.b64 %0, {%1, %2};" : "=l"(r) : "f"(lo), "f"(hi)); return r;
}
__device__ __forceinline__ void upk2(ull v, float& lo, float& hi) {
    asm("mov.b64 {%0, %1}, %2;" : "=f"(lo), "=f"(hi) : "l"(v));
}
__device__ __forceinline__ ull ffma2(ull a, ull b, ull c) {
    ull d; asm("fma.rn.f32x2 %0, %1, %2, %3;" : "=l"(d) : "l"(a), "l"(b), "l"(c)); return d;
}

// bf16x2 pack/unpack
__device__ __forceinline__ unsigned pack_bf2(float lo, float hi) {
    unsigned r; asm("cvt.rn.bf16x2.f32 %0, %1, %2;" : "=r"(r) : "f"(hi), "f"(lo)); return r;
}
__device__ __forceinline__ float bf_lo(unsigned u) { return __uint_as_float(u << 16); }
__device__ __forceinline__ float bf_hi(unsigned u) { return __uint_as_float(u & 0xffff0000u); }

// monotone 16-bit key for bf16 bits
__device__ __forceinline__ unsigned key16(unsigned u16) {
    return (u16 & 0x8000u) ? (u16 ^ 0xffffu) : (u16 | 0x8000u);
}

__device__ __forceinline__ void mma_bf16(float& c0, float& c1, float& c2, float& c3,
                                         unsigned a0, unsigned a1, unsigned a2, unsigned a3,
                                         unsigned b0, unsigned b1) {
    asm volatile("mma.sync.aligned.m16n8k16.row.col.f32.bf16.bf16.f32 "
                 "{%0,%1,%2,%3}, {%4,%5,%6,%7}, {%8,%9}, {%0,%1,%2,%3};"
                 : "+f"(c0), "+f"(c1), "+f"(c2), "+f"(c3)
                 : "r"(a0), "r"(a1), "r"(a2), "r"(a3), "r"(b0), "r"(b1));
}

// =================================================================
// Kernel 1: qkv = depthwise3x3(pwconv_group4(x, w)), fused per (b,c)
// k gets per-channel L2 norm applied and is written transposed bf16.
// =================================================================
__global__ __launch_bounds__(256) void qkv_kernel(
    const float* __restrict__ x,
    const float* __restrict__ wq, const float* __restrict__ wk, const float* __restrict__ wv,
    const float* __restrict__ dwq, const float* __restrict__ dwk, const float* __restrict__ dwv)
{
    __shared__ float sq[NTOK], sk[NTOK], sv[NTOK];
    __shared__ float wpq[32], wpk[32], wpv[32];
    __shared__ float wdq[9], wdk[9], wdv[9];
    __shared__ float red[256];
    __shared__ float s_scale;

    const int b = blockIdx.x >> 7;
    const int c = blockIdx.x & 127;
    const int g = c >> 5;
    const int tid = threadIdx.x;

    if (tid < 32) {
        wpq[tid] = wq[c*32 + tid];
        wpk[tid] = wk[c*32 + tid];
        wpv[tid] = wv[c*32 + tid];
    }
    if (tid < 9) {
        wdq[tid] = dwq[c*9 + tid];
        wdk[tid] = dwk[c*9 + tid];
        wdv[tid] = dwv[c*9 + tid];
    }
    __syncthreads();

    const float* xb = x + (size_t)(b*CC + g*32) * NTOK;
    float aq[9], ak[9], av[9];
#pragma unroll
    for (int p = 0; p < 9; ++p) { aq[p] = 0.f; ak[p] = 0.f; av[p] = 0.f; }
    for (int i = 0; i < 32; ++i) {
        const float wq_i = wpq[i], wk_i = wpk[i], wv_i = wpv[i];
        const float* xi = xb + i*NTOK;
#pragma unroll
        for (int p = 0; p < 9; ++p) {
            float xv = xi[tid + p*256];
            aq[p] += wq_i*xv; ak[p] += wk_i*xv; av[p] += wv_i*xv;
        }
    }
#pragma unroll
    for (int p = 0; p < 9; ++p) {
        int n = tid + p*256;
        sq[n] = aq[p]; sk[n] = ak[p]; sv[n] = av[p];
    }
    __syncthreads();

    float dq[9], dk[9], dv[9];
    float kss = 0.f;
#pragma unroll
    for (int p = 0; p < 9; ++p) {
        int n = tid + p*256;
        int r = n / HH;
        int col = n - r*HH;
        float s0 = 0.f, s1 = 0.f, s2 = 0.f;
#pragma unroll
        for (int dy = 0; dy < 3; ++dy) {
            int rr = r + dy - 1;
            if ((unsigned)rr < (unsigned)HH) {
#pragma unroll
                for (int dx = 0; dx < 3; ++dx) {
                    int cc2 = col + dx - 1;
                    if ((unsigned)cc2 < (unsigned)HH) {
                        int nn = rr*HH + cc2;
                        s0 += wdq[dy*3+dx] * sq[nn];
                        s1 += wdk[dy*3+dx] * sk[nn];
                        s2 += wdv[dy*3+dx] * sv[nn];
                    }
                }
            }
        }
        dq[p] = s0; dk[p] = s1; dv[p] = s2;
        kss += s1 * s1;
    }

    red[tid] = kss;
    __syncthreads();
#pragma unroll
    for (int s = 128; s > 0; s >>= 1) {
        if (tid < s) red[tid] += red[tid + s];
        __syncthreads();
    }
    if (tid == 0) s_scale = 1.f / fmaxf(sqrtf(red[0]), 1e-12f);
    __syncthreads();
    const float sc = s_scale;

    const size_t base = (size_t)(b*CC + c) * NTOK;
    const int bh = b*NHEADS + (c >> 4);
    const int ch = c & 15;
    __nv_bfloat16* kT = g_kT + (size_t)bh * NTOK * CHH + ch;
#pragma unroll
    for (int p = 0; p < 9; ++p) {
        int n = tid + p*256;
        g_q[base + n] = dq[p];
        kT[(size_t)n * CHH] = __float2bfloat16(dk[p] * sc);
        g_v16[base + n] = __float2bfloat16(dv[p]);
    }
}

// =================================================================
// Kernel 2: fused attention, tensor-core bf16.
// grid = (NTOK/16 row tiles, B*NHEADS), 512 threads (16 warps)
// =================================================================
#define SROW_U32 1156                      // 1152 + 4 pad (bank spread)
#define ATTN_SM_S    (16*SROW_U32*4)       // 73984 bf16 scores/weights
#define ATTN_SM_QA   512                   // 16x16 bf16 A fragment source
#define ATTN_SM_HIST (16*256*4)            // radix hist / PV reduce scratch
#define ATTN_SM_RST  64                    // invz[16]
#define ATTN_SMEM_BYTES (ATTN_SM_S + ATTN_SM_QA + ATTN_SM_HIST + ATTN_SM_RST)

// parallel "find bin from top" over 256 bins; updates kk, returns bin
__device__ __forceinline__ unsigned find_bin(const unsigned* hw, int lane, int& kk) {
    int base = lane * 8;
    unsigned l[8];
    int ls = 0;
#pragma unroll
    for (int i = 0; i < 8; ++i) { l[i] = hw[base + i]; ls += l[i]; }
    int suf = ls;
#pragma unroll
    for (int off = 1; off < 32; off <<= 1) {
        int v = __shfl_down_sync(0xffffffffu, suf, off);
        if (lane + off < 32) suf += v;
    }
    int above = suf - ls;
    bool found = (suf >= kk) && (above < kk);
    unsigned bal = __ballot_sync(0xffffffffu, found);
    int fl = __ffs(bal) - 1;
    int dloc = 0, kkloc = 0;
    if (found) {
        int cum = above;
#pragma unroll
        for (int i = 7; i >= 0; --i) {
            cum += (int)l[i];
            if (cum >= kk) { dloc = base + i; kkloc = kk - (cum - (int)l[i]); break; }
        }
    }
    unsigned d = (unsigned)__shfl_sync(0xffffffffu, dloc, fl);
    kk = __shfl_sync(0xffffffffu, kkloc, fl);
    return d;
}

__global__ __launch_bounds__(512, 2) void attn_kernel(const float* __restrict__ temperature)
{
    extern __shared__ unsigned char smraw[];
    unsigned* sU = (unsigned*)smraw;                               // scores/weights u32 view
    __nv_bfloat16* qA = (__nv_bfloat16*)(smraw + ATTN_SM_S);       // [16][16]
    unsigned* hist = (unsigned*)(smraw + ATTN_SM_S + ATTN_SM_QA);  // [16][256]
    float* scratch = (float*)hist;                                 // alias (after select)
    float* invz = (float*)(smraw + ATTN_SM_S + ATTN_SM_QA + ATTN_SM_HIST);

    const int rt = blockIdx.x, bh = blockIdx.y;
    const int b = bh >> 3, h = bh & 7;
    const int bc0 = b*CC + h*CHH;
    const int row0 = rt * 16;
    const int tid = threadIdx.x;
    const int w = tid >> 5, lane = tid & 31;
    const float ts = temperature[h];

    // ---- phase 0: load Q rows, L2-normalize over C_h, fold temperature ----
    if (tid < 256) {
        int r = tid >> 4, c = tid & 15;
        float qv = g_q[(size_t)(bc0 + c)*NTOK + row0 + r];
        float ss = qv * qv;
#pragma unroll
        for (int off = 8; off; off >>= 1) ss += __shfl_xor_sync(0xffffffffu, ss, off, 16);
        qA[r*16 + c] = __float2bfloat16(qv * ts / fmaxf(sqrtf(ss), 1e-12f));
    }
    __syncthreads();

    // ---- phase 1: scores via mma, warp w owns cols [w*144, w*144+144) ----
    unsigned a0, a1, a2, a3;
    {
        const unsigned* qAu = (const unsigned*)qA;
        int r = lane >> 2, kx = (lane & 3) * 2;
        a0 = qAu[(r*16 + kx) >> 1];
        a1 = qAu[((r+8)*16 + kx) >> 1];
        a2 = qAu[(r*16 + kx + 8) >> 1];
        a3 = qAu[((r+8)*16 + kx + 8) >> 1];
    }
    {
        const unsigned* kTu = (const unsigned*)(g_kT + (size_t)bh * NTOK * CHH);
        const int jl = lane >> 2, ko = lane & 3;
        const int r = lane >> 2, cst = (lane & 3) * 2;
#pragma unroll 3
        for (int m = 0; m < 18; ++m) {
            int j0 = w*144 + m*8;
            const unsigned* kp = kTu + (size_t)(j0 + jl)*8 + ko;
            unsigned b0 = kp[0];
            unsigned b1 = kp[4];
            float c0 = 0.f, c1 = 0.f, c2 = 0.f, c3 = 0.f;
            mma_bf16(c0, c1, c2, c3, a0, a1, a2, a3, b0, b1);
            int ju = (j0 >> 1) + (cst >> 1);
            sU[r*SROW_U32 + ju]     = pack_bf2(c0, c1);
            sU[(r+8)*SROW_U32 + ju] = pack_bf2(c2, c3);
        }
    }
    __syncthreads();

    // ---- phase 2: per-row (warp) max + 2-pass 8-bit radix select on bf16 keys ----
    unsigned* srowU = sU + w*SROW_U32;
    unsigned* hw = hist + w*256;
#pragma unroll
    for (int i = lane; i < 256; i += 32) hw[i] = 0;
    __syncwarp();

    float rmax = -3.4e38f;
    for (int it = 0; it < 36; ++it) {
        unsigned u = srowU[lane + it*32];
        rmax = fmaxf(rmax, fmaxf(bf_lo(u), bf_hi(u)));
        unsigned h0 = key16(u & 0xffffu) >> 8;
        unsigned h1 = key16(u >> 16) >> 8;
        unsigned mm = __match_any_sync(0xffffffffu, h0);
        if ((mm & ((1u << lane) - 1u)) == 0) atomicAdd(&hw[h0], __popc(mm));
        mm = __match_any_sync(0xffffffffu, h1);
        if ((mm & ((1u << lane) - 1u)) == 0) atomicAdd(&hw[h1], __popc(mm));
    }
#pragma unroll
    for (int off = 16; off; off >>= 1) rmax = fmaxf(rmax, __shfl_xor_sync(0xffffffffu, rmax, off));
    __syncwarp();

    int kk = KTOP;
    unsigned dhi = find_bin(hw, lane, kk);

#pragma unroll
    for (int i = lane; i < 256; i += 32) hw[i] = 0;
    __syncwarp();
    for (int it = 0; it < 36; ++it) {
        unsigned u = srowU[lane + it*32];
        unsigned k0 = key16(u & 0xffffu);
        unsigned k1 = key16(u >> 16);
        if ((k0 >> 8) == dhi) atomicAdd(&hw[k0 & 255u], 1u);
        if ((k1 >> 8) == dhi) atomicAdd(&hw[k1 & 255u], 1u);
    }
    __syncwarp();
    unsigned dlo = find_bin(hw, lane, kk);

    unsigned tkey = (dhi << 8) | dlo;
    unsigned tb = (tkey & 0x8000u) ? (tkey ^ 0x8000u) : (tkey ^ 0xffffu);
    const float tthr = __uint_as_float(tb << 16);

    // ---- phase 3: masked softmax weights (bf16, in place), accumulate Z ----
    float z = 0.f;
    for (int it = 0; it < 36; ++it) {
        unsigned u = srowU[lane + it*32];
        float f0 = bf_lo(u), f1 = bf_hi(u);
        float w0 = (f0 >= tthr) ? __expf(f0 - rmax) : 0.f;
        float w1 = (f1 >= tthr) ? __expf(f1 - rmax) : 0.f;
        z += w0 + w1;
        srowU[lane + it*32] = pack_bf2(w0, w1);
    }
#pragma unroll
    for (int off = 16; off; off >>= 1) z += __shfl_xor_sync(0xffffffffu, z, off);
    if (lane == 0) invz[w] = 1.f / z;
    __syncthreads();   // all weights visible; hist region now dead -> scratch

    // ---- phase 4: PV via mma, warp w owns token stripe [w*144, +144) ----
    float acc[8];
#pragma unroll
    for (int i = 0; i < 8; ++i) acc[i] = 0.f;
    {
        const __nv_bfloat16* vb = g_v16 + (size_t)bc0 * NTOK;
        const int r = lane >> 2, kx = (lane & 3) * 2;
#pragma unroll 3
        for (int cnk = 0; cnk < 9; ++cnk) {
            int k0 = w*144 + cnk*16;
            unsigned A0 = sU[r*SROW_U32 + ((k0 + kx) >> 1)];
            unsigned A1 = sU[(r+8)*SROW_U32 + ((k0 + kx) >> 1)];
            unsigned A2 = sU[r*SROW_U32 + ((k0 + kx + 8) >> 1)];
            unsigned A3 = sU[(r+8)*SROW_U32 + ((k0 + kx + 8) >> 1)];
            unsigned B0 = *(const unsigned*)(vb + (size_t)r*NTOK + k0 + kx);
            unsigned B1 = *(const unsigned*)(vb + (size_t)r*NTOK + k0 + kx + 8);
            mma_bf16(acc[0], acc[1], acc[2], acc[3], A0, A1, A2, A3, B0, B1);
            unsigned B2 = *(const unsigned*)(vb + (size_t)(r+8)*NTOK + k0 + kx);
            unsigned B3 = *(const unsigned*)(vb + (size_t)(r+8)*NTOK + k0 + kx + 8);
            mma_bf16(acc[4], acc[5], acc[6], acc[7], A0, A1, A2, A3, B2, B3);
        }
    }
    {
        int r = lane >> 2, c2 = (lane & 3) * 2;
        float* sw = scratch + w*256;
        sw[r*16 + c2]           = acc[0];
        sw[r*16 + c2 + 1]       = acc[1];
        sw[(r+8)*16 + c2]       = acc[2];
        sw[(r+8)*16 + c2 + 1]   = acc[3];
        sw[r*16 + 8 + c2]       = acc[4];
        sw[r*16 + 8 + c2 + 1]   = acc[5];
        sw[(r+8)*16 + 8 + c2]   = acc[6];
        sw[(r+8)*16 + 8 + c2+1] = acc[7];
    }
    __syncthreads();

    // ---- phase 5: cross-warp reduce + write ----
    if (tid < 256) {
        int r = tid >> 4, c = tid & 15;
        float s = 0.f;
#pragma unroll
        for (int wi = 0; wi < 16; ++wi) s += scratch[wi*256 + r*16 + c];
        g_attn[(size_t)(bc0 + c)*NTOK + row0 + r] = s * invz[r];
    }
}

// =================================================================
// Kernel 3: out = x + wo(128x128) @ attn_out   (1x1 conv + residual)
// =================================================================
#define OC_SMEM_FLOATS (16384 + 32*130)
#define OC_SMEM_BYTES  (OC_SMEM_FLOATS * 4)

__global__ __launch_bounds__(256) void outconv_kernel(
    const float* __restrict__ x, const float* __restrict__ wo, float* __restrict__ out)
{
    extern __shared__ float sm3[];
    float* wo_s = sm3;             // 128*128
    float* af   = sm3 + 16384;     // transposed attn tile [n(32)][c(128)] stride 130

    const int b  = blockIdx.y;
    const int n0 = blockIdx.x * 32;
    const int tid = threadIdx.x;

    for (int l = tid; l < 16384; l += 256) wo_s[l] = wo[l];
    for (int l = tid; l < 4096; l += 256) {
        int cc2 = l >> 5, nl = l & 31;
        af[nl*130 + cc2] = g_attn[(size_t)(b*CC + cc2)*NTOK + n0 + nl];
    }
    __syncthreads();

    const int lane = tid & 31;
    const int w = tid >> 5;
    const ull* arow = reinterpret_cast<const ull*>(af + lane*130);
    const ull* wou = reinterpret_cast<const ull*>(wo_s);

    ull acc[16];
#pragma unroll
    for (int k = 0; k < 16; ++k) acc[k] = 0ull;

    for (int cp = 0; cp < 64; ++cp) {
        ull av2 = arow[cp];
#pragma unroll
        for (int k = 0; k < 16; ++k)
            acc[k] = ffma2(wou[(w*16 + k)*64 + cp], av2, acc[k]);
    }

#pragma unroll
    for (int k = 0; k < 16; ++k) {
        float lo, hi; upk2(acc[k], lo, hi);
        float s = lo + hi;
        int co = w*16 + k;
        size_t idx = (size_t)(b*CC + co)*NTOK + n0 + lane;
        out[idx] = x[idx] + s;
    }
}

// =================================================================
extern "C" void kernel_launch(void* const* d_in, const int* in_sizes, int n_in,
                              void* d_out, int out_size)
{
    const float* x    = (const float*)d_in[0];
    const float* wq   = (const float*)d_in[1];
    const float* wk   = (const float*)d_in[2];
    const float* wv   = (const float*)d_in[3];
    const float* dwq  = (const float*)d_in[4];
    const float* dwk  = (const float*)d_in[5];
    const float* dwv  = (const float*)d_in[6];
    const float* wo   = (const float*)d_in[7];
    const float* temp = (const float*)d_in[8];
    float* out = (float*)d_out;

    cudaFuncSetAttribute(attn_kernel, cudaFuncAttributeMaxDynamicSharedMemorySize, ATTN_SMEM_BYTES);
    cudaFuncSetAttribute(outconv_kernel, cudaFuncAttributeMaxDynamicSharedMemorySize, OC_SMEM_BYTES);

    qkv_kernel<<<BB*CC, 256>>>(x, wq, wk, wv, dwq, dwk, dwv);
    attn_kernel<<<dim3(NTOK/16, BB*NHEADS), 512, ATTN_SMEM_BYTES>>>(temp);
    outconv_kernel<<<dim3(NTOK/32, BB), 256, OC_SMEM_BYTES>>>(x, wo, out);
}

// round 4
// speedup vs baseline: 1.2089x; 1.2089x over previous
#include <cuda_runtime.h>
#include <cuda_bf16.h>
#include <cuda_fp8.h>
#include <cstdint>

#define BB   2
#define CC   128
#define HH   48
#define NTOK 2304
#define NHEADS 8
#define CHH  16
#define KTOP 1843

typedef unsigned long long ull;

// ---------------- scratch ----------------
__device__ float g_q[BB*CC*NTOK];
__device__ __nv_bfloat16 g_kT[BB*NHEADS*NTOK*CHH];   // normalized K, [bh][n][ch]
__device__ unsigned char g_v8[BB*CC*NTOK];           // v e4m3 (scaled)
__device__ float g_vsinv[BB*CC];                     // per-channel V inverse scale
__device__ float g_attn[BB*CC*NTOK];

// ---------------- f32x2 helpers ----------------
__device__ __forceinline__ void upk2(ull v, float& lo, float& hi) {
    asm("mov.b64 {%0, %1}, %2;" : "=f"(lo), "=f"(hi) : "l"(v));
}
__device__ __forceinline__ ull ffma2(ull a, ull b, ull c) {
    ull d; asm("fma.rn.f32x2 %0, %1, %2, %3;" : "=l"(d) : "l"(a), "l"(b), "l"(c)); return d;
}

// ---------------- fp8 helpers ----------------
__device__ __forceinline__ unsigned short pack2_e4m3(float lo, float hi) {
    unsigned short r;
    asm("cvt.rn.satfinite.e4m3x2.f32 %0, %1, %2;" : "=h"(r) : "f"(hi), "f"(lo));
    return r;   // low byte = lo
}
__device__ __forceinline__ void deq2_e4m3(unsigned short b2, float& lo, float& hi) {
    unsigned h2;
    asm("cvt.rn.f16x2.e4m3x2 %0, %1;" : "=r"(h2) : "h"(b2));
    __half2 hh = *reinterpret_cast<__half2*>(&h2);
    lo = __low2float(hh); hi = __high2float(hh);
}
__device__ __forceinline__ unsigned f2e4m3(float f) {
    return (unsigned)__nv_cvt_float_to_fp8(f, __NV_SATFINITE, __NV_E4M3);
}
__device__ __forceinline__ float e4m32f(unsigned b) {
    __half_raw hr = __nv_cvt_fp8_to_halfraw((__nv_fp8_storage_t)b, __NV_E4M3);
    return __half2float(*reinterpret_cast<__half*>(&hr));
}
// monotone 8-bit keys over 4 packed e4m3 bytes; inverse for one byte
__device__ __forceinline__ unsigned keymap4(unsigned u) {
    unsigned m = u & 0x80808080u;
    unsigned X = 0x80808080u | ((m >> 7) * 0x7Fu);
    return u ^ X;
}
__device__ __forceinline__ unsigned kinv8(unsigned k) {
    return (k & 0x80u) ? (k ^ 0x80u) : ((~k) & 0xFFu);
}

// ---------------- mma wrappers ----------------
__device__ __forceinline__ void mma_bf16(float& c0, float& c1, float& c2, float& c3,
                                         unsigned a0, unsigned a1, unsigned a2, unsigned a3,
                                         unsigned b0, unsigned b1) {
    asm volatile("mma.sync.aligned.m16n8k16.row.col.f32.bf16.bf16.f32 "
                 "{%0,%1,%2,%3}, {%4,%5,%6,%7}, {%8,%9}, {%0,%1,%2,%3};"
                 : "+f"(c0), "+f"(c1), "+f"(c2), "+f"(c3)
                 : "r"(a0), "r"(a1), "r"(a2), "r"(a3), "r"(b0), "r"(b1));
}
__device__ __forceinline__ void mma_e4m3(float& c0, float& c1, float& c2, float& c3,
                                         unsigned a0, unsigned a1, unsigned a2, unsigned a3,
                                         unsigned b0, unsigned b1) {
    asm volatile("mma.sync.aligned.m16n8k32.row.col.f32.e4m3.e4m3.f32 "
                 "{%0,%1,%2,%3}, {%4,%5,%6,%7}, {%8,%9}, {%0,%1,%2,%3};"
                 : "+f"(c0), "+f"(c1), "+f"(c2), "+f"(c3)
                 : "r"(a0), "r"(a1), "r"(a2), "r"(a3), "r"(b0), "r"(b1));
}

// ---------------- register 16-bin counting helpers ----------------
__device__ __forceinline__ void cadd(unsigned b, unsigned& c0, unsigned& c1,
                                     unsigned& c2, unsigned& c3) {
    unsigned val = 1u << ((b & 3u) << 3);
    if (b < 4u) c0 += val; else if (b < 8u) c1 += val;
    else if (b < 12u) c2 += val; else c3 += val;
}
__device__ __forceinline__ void red16(unsigned c0, unsigned c1, unsigned c2, unsigned c3,
                                      unsigned e[8]) {
    e[0] = c0 & 0x00FF00FFu; e[1] = (c0 >> 8) & 0x00FF00FFu;
    e[2] = c1 & 0x00FF00FFu; e[3] = (c1 >> 8) & 0x00FF00FFu;
    e[4] = c2 & 0x00FF00FFu; e[5] = (c2 >> 8) & 0x00FF00FFu;
    e[6] = c3 & 0x00FF00FFu; e[7] = (c3 >> 8) & 0x00FF00FFu;
#pragma unroll
    for (int off = 16; off; off >>= 1) {
#pragma unroll
        for (int j = 0; j < 8; ++j) e[j] += __shfl_xor_sync(0xffffffffu, e[j], off);
    }
}
// bin b=4i+j lives in counter i, byte j -> e[2i+(j&1)], halfword (j>>1)
__device__ __forceinline__ int pick16(const unsigned e[8], int& kk) {
    int h[16];
#pragma unroll
    for (int i = 0; i < 4; ++i)
#pragma unroll
        for (int j = 0; j < 4; ++j)
            h[4*i+j] = (int)((e[2*i + (j&1)] >> (16*(j>>1))) & 0xffffu);
    int cum = 0, d = 0, kkr = kk;
#pragma unroll
    for (int i = 15; i >= 0; --i) {
        int ncum = cum + h[i];
        if (cum < kk && ncum >= kk) { d = i; kkr = kk - cum; }
        cum = ncum;
    }
    kk = kkr;
    return d;
}

// =================================================================
// Kernel 1: per (b,c,type) conv chain. blockIdx.y: 0=q, 1=k, 2=v
// =================================================================
__global__ __launch_bounds__(256) void qkv_kernel(
    const float* __restrict__ x,
    const float* __restrict__ wq, const float* __restrict__ wk, const float* __restrict__ wv,
    const float* __restrict__ dwq, const float* __restrict__ dwk, const float* __restrict__ dwv)
{
    __shared__ float sp[NTOK];
    __shared__ float wp[32];
    __shared__ float wd[9];
    __shared__ float red[256];
    __shared__ float s_scale;

    const int t = blockIdx.y;
    const int b = blockIdx.x >> 7;
    const int c = blockIdx.x & 127;
    const int g = c >> 5;
    const int tid = threadIdx.x;

    const float* wsel = (t == 0) ? wq : (t == 1) ? wk : wv;
    const float* dsel = (t == 0) ? dwq : (t == 1) ? dwk : dwv;

    if (tid < 32) wp[tid] = wsel[c*32 + tid];
    if (tid < 9)  wd[tid] = dsel[c*9 + tid];
    __syncthreads();

    const float* xb = x + (size_t)(b*CC + g*32) * NTOK;
    float a[9];
#pragma unroll
    for (int p = 0; p < 9; ++p) a[p] = 0.f;
    for (int i = 0; i < 32; ++i) {
        const float wi = wp[i];
        const float* xi = xb + i*NTOK;
#pragma unroll
        for (int p = 0; p < 9; ++p) a[p] += wi * xi[tid + p*256];
    }
#pragma unroll
    for (int p = 0; p < 9; ++p) sp[tid + p*256] = a[p];
    __syncthreads();

    float d[9];
    float rv = 0.f;
#pragma unroll
    for (int p = 0; p < 9; ++p) {
        int n = tid + p*256;
        int r = n / HH;
        int col = n - r*HH;
        float s = 0.f;
#pragma unroll
        for (int dy = 0; dy < 3; ++dy) {
            int rr = r + dy - 1;
            if ((unsigned)rr < (unsigned)HH) {
#pragma unroll
                for (int dx = 0; dx < 3; ++dx) {
                    int cc2 = col + dx - 1;
                    if ((unsigned)cc2 < (unsigned)HH)
                        s += wd[dy*3+dx] * sp[rr*HH + cc2];
                }
            }
        }
        d[p] = s;
        if (t == 1) rv += s * s;
        else if (t == 2) rv = fmaxf(rv, fabsf(s));
    }

    if (t != 0) {
        red[tid] = rv;
        __syncthreads();
#pragma unroll
        for (int s = 128; s > 0; s >>= 1) {
            if (tid < s) red[tid] = (t == 2) ? fmaxf(red[tid], red[tid+s]) : (red[tid] + red[tid+s]);
            __syncthreads();
        }
        if (tid == 0) {
            if (t == 1) s_scale = 1.f / fmaxf(sqrtf(red[0]), 1e-12f);
            else {
                float mx = red[0];
                s_scale = (mx > 0.f) ? 240.f / mx : 0.f;
                g_vsinv[b*CC + c] = (mx > 0.f) ? mx / 240.f : 0.f;
            }
        }
        __syncthreads();
    }

    const size_t base = (size_t)(b*CC + c) * NTOK;
    if (t == 0) {
#pragma unroll
        for (int p = 0; p < 9; ++p) g_q[base + tid + p*256] = d[p];
    } else if (t == 1) {
        const float sc = s_scale;
        const int bh = b*NHEADS + (c >> 4);
        const int ch = c & 15;
        __nv_bfloat16* kT = g_kT + (size_t)bh * NTOK * CHH + ch;
#pragma unroll
        for (int p = 0; p < 9; ++p)
            kT[(size_t)(tid + p*256) * CHH] = __float2bfloat16(d[p] * sc);
    } else {
        const float sc = s_scale;
#pragma unroll
        for (int p = 0; p < 9; ++p)
            g_v8[base + tid + p*256] = (unsigned char)f2e4m3(d[p] * sc);
    }
}

// =================================================================
// Kernel 2: fused attention. fp8 scores + register radix select.
// grid = (144, 16), 512 threads (16 warps; warp w owns query row w)
// =================================================================
#define SROWB 2320                          // 2304 + 16 pad
#define ATTN_SM_S   (16*SROWB)              // 37120
#define ATTN_SM_QA  512
#define ATTN_SM_SCR (16*256*4)              // 16384
#define ATTN_SM_RST 64
#define ATTN_SMEM_BYTES (ATTN_SM_S + ATTN_SM_QA + ATTN_SM_SCR + ATTN_SM_RST)

__global__ __launch_bounds__(512, 2) void attn_kernel(const float* __restrict__ temperature)
{
    extern __shared__ unsigned char smraw[];
    unsigned char* smS = smraw;
    __nv_bfloat16* qA  = (__nv_bfloat16*)(smraw + ATTN_SM_S);
    float* scratch     = (float*)(smraw + ATTN_SM_S + ATTN_SM_QA);
    float* invz        = (float*)(smraw + ATTN_SM_S + ATTN_SM_QA + ATTN_SM_SCR);

    const int rt = blockIdx.x, bh = blockIdx.y;
    const int b = bh >> 3, h = bh & 7;
    const int bc0 = b*CC + h*CHH;
    const int row0 = rt * 16;
    const int tid = threadIdx.x;
    const int w = tid >> 5, lane = tid & 31;
    const float ts = temperature[h];

    // ---- phase 0: Q rows, L2-normalize over C_h, fold temperature ----
    if (tid < 256) {
        int r = tid >> 4, c = tid & 15;
        float qv = g_q[(size_t)(bc0 + c)*NTOK + row0 + r];
        float ss = qv * qv;
#pragma unroll
        for (int off = 8; off; off >>= 1) ss += __shfl_xor_sync(0xffffffffu, ss, off, 16);
        qA[r*16 + c] = __float2bfloat16(qv * ts / fmaxf(sqrtf(ss), 1e-12f));
    }
    __syncthreads();

    // ---- phase 1: scores via bf16 mma -> e4m3 smem. warp stripe 144 cols ----
    {
        const unsigned* qAu = (const unsigned*)qA;
        int r = lane >> 2, kx = (lane & 3) * 2;
        unsigned a0 = qAu[(r*16 + kx) >> 1];
        unsigned a1 = qAu[((r+8)*16 + kx) >> 1];
        unsigned a2 = qAu[(r*16 + kx + 8) >> 1];
        unsigned a3 = qAu[((r+8)*16 + kx + 8) >> 1];

        const unsigned* kTu = (const unsigned*)(g_kT + (size_t)bh * NTOK * CHH);
        const int jl = lane >> 2, ko = lane & 3;
        const int cst = (lane & 3) * 2;
#pragma unroll 3
        for (int m = 0; m < 18; ++m) {
            int j0 = w*144 + m*8;
            const unsigned* kp = kTu + (size_t)(j0 + jl)*8 + ko;
            unsigned b0 = kp[0];
            unsigned b1 = kp[4];
            float c0 = 0.f, c1 = 0.f, c2 = 0.f, c3 = 0.f;
            mma_bf16(c0, c1, c2, c3, a0, a1, a2, a3, b0, b1);
            int off = j0 + cst;
            *(unsigned short*)(smS + r*SROWB + off)     = pack2_e4m3(c0, c1);
            *(unsigned short*)(smS + (r+8)*SROWB + off) = pack2_e4m3(c2, c3);
        }
    }
    __syncthreads();

    // ---- phase 2: register nibble-radix select (no atomics) ----
    unsigned* srowU = (unsigned*)(smS + (size_t)w * SROWB);
    unsigned c0 = 0, c1 = 0, c2 = 0, c3 = 0, maxk = 0;
#pragma unroll 6
    for (int it = 0; it < 18; ++it) {
        unsigned k4 = keymap4(srowU[lane + it*32]);
        maxk = __vmaxu4(maxk, k4);
#pragma unroll
        for (int i = 0; i < 4; ++i)
            cadd((k4 >> (8*i + 4)) & 0xFu, c0, c1, c2, c3);
    }
#pragma unroll
    for (int off = 16; off; off >>= 1)
        maxk = __vmaxu4(maxk, __shfl_xor_sync(0xffffffffu, maxk, off));
    {
        unsigned mb = maxk;
        mb = (mb > (mb >> 16)) ? mb : (mb >> 16);
        unsigned lo8 = mb & 0xFFu, hi8 = (mb >> 8) & 0xFFu;
        maxk = (lo8 > hi8) ? lo8 : hi8;
    }
    const float rmax = e4m32f(kinv8(maxk));

    unsigned e[8];
    red16(c0, c1, c2, c3, e);
    int kk = KTOP;
    const unsigned d1 = (unsigned)pick16(e, kk);

    c0 = c1 = c2 = c3 = 0;
#pragma unroll 6
    for (int it = 0; it < 18; ++it) {
        unsigned k4 = keymap4(srowU[lane + it*32]);
#pragma unroll
        for (int i = 0; i < 4; ++i) {
            unsigned kb = (k4 >> (8*i)) & 0xFFu;
            if ((kb >> 4) == d1) cadd(kb & 0xFu, c0, c1, c2, c3);
        }
    }
    red16(c0, c1, c2, c3, e);
    const unsigned d2 = (unsigned)pick16(e, kk);
    const unsigned tk = (d1 << 4) | d2;

    // ---- phase 3: masked softmax -> e4m3 weights in place ----
    float z = 0.f;
#pragma unroll 4
    for (int it = 0; it < 18; ++it) {
        unsigned u = srowU[lane + it*32];
        unsigned k4 = keymap4(u);
        float f0, f1, f2, f3;
        deq2_e4m3((unsigned short)(u & 0xffffu), f0, f1);
        deq2_e4m3((unsigned short)(u >> 16), f2, f3);
        float w0 = (((k4      ) & 0xFFu) >= tk) ? __expf(f0 - rmax) : 0.f;
        float w1 = (((k4 >>  8) & 0xFFu) >= tk) ? __expf(f1 - rmax) : 0.f;
        float w2 = (((k4 >> 16) & 0xFFu) >= tk) ? __expf(f2 - rmax) : 0.f;
        float w3 = (((k4 >> 24) & 0xFFu) >= tk) ? __expf(f3 - rmax) : 0.f;
        z += (w0 + w1) + (w2 + w3);
        unsigned s0 = (unsigned)pack2_e4m3(w0, w1);
        unsigned s1 = (unsigned)pack2_e4m3(w2, w3);
        srowU[lane + it*32] = s0 | (s1 << 16);
    }
#pragma unroll
    for (int off = 16; off; off >>= 1) z += __shfl_xor_sync(0xffffffffu, z, off);
    if (lane == 0) invz[w] = 1.f / z;
    __syncthreads();

    // ---- phase 4: PV via fp8 mma, warp strides 512-token chunks ----
    float acc[8];
#pragma unroll
    for (int i = 0; i < 8; ++i) acc[i] = 0.f;
    {
        const unsigned char* vb = g_v8 + (size_t)bc0 * NTOK;
        const int r = lane >> 2, kx = (lane & 3) * 4;
        const int nn = lane >> 2;
        for (int k0 = w*32; k0 < NTOK; k0 += 512) {
            unsigned A0 = *(const unsigned*)(smS + r*SROWB + k0 + kx);
            unsigned A1 = *(const unsigned*)(smS + (r+8)*SROWB + k0 + kx);
            unsigned A2 = *(const unsigned*)(smS + r*SROWB + k0 + kx + 16);
            unsigned A3 = *(const unsigned*)(smS + (r+8)*SROWB + k0 + kx + 16);
            unsigned B0 = *(const unsigned*)(vb + (size_t)nn*NTOK + k0 + kx);
            unsigned B1 = *(const unsigned*)(vb + (size_t)nn*NTOK + k0 + kx + 16);
            mma_e4m3(acc[0], acc[1], acc[2], acc[3], A0, A1, A2, A3, B0, B1);
            unsigned B2 = *(const unsigned*)(vb + (size_t)(nn+8)*NTOK + k0 + kx);
            unsigned B3 = *(const unsigned*)(vb + (size_t)(nn+8)*NTOK + k0 + kx + 16);
            mma_e4m3(acc[4], acc[5], acc[6], acc[7], A0, A1, A2, A3, B2, B3);
        }
    }
    {
        int r = lane >> 2, c2s = (lane & 3) * 2;
        float* sw = scratch + w*256;
        sw[r*16 + c2s]           = acc[0];
        sw[r*16 + c2s + 1]       = acc[1];
        sw[(r+8)*16 + c2s]       = acc[2];
        sw[(r+8)*16 + c2s + 1]   = acc[3];
        sw[r*16 + 8 + c2s]       = acc[4];
        sw[r*16 + 8 + c2s + 1]   = acc[5];
        sw[(r+8)*16 + 8 + c2s]   = acc[6];
        sw[(r+8)*16 + 8 + c2s+1] = acc[7];
    }
    __syncthreads();

    // ---- phase 5: cross-warp reduce, unscale, write ----
    if (tid < 256) {
        int r = tid >> 4, c = tid & 15;
        float s = 0.f;
#pragma unroll
        for (int wi = 0; wi < 16; ++wi) s += scratch[wi*256 + r*16 + c];
        g_attn[(size_t)(bc0 + c)*NTOK + row0 + r] = s * invz[r] * g_vsinv[bc0 + c];
    }
}

// =================================================================
// Kernel 3: out = x + wo @ attn  (1x1 conv + residual)
// =================================================================
#define OC_SMEM_FLOATS (16384 + 32*130)
#define OC_SMEM_BYTES  (OC_SMEM_FLOATS * 4)

__global__ __launch_bounds__(256) void outconv_kernel(
    const float* __restrict__ x, const float* __restrict__ wo, float* __restrict__ out)
{
    extern __shared__ float sm3[];
    float* wo_s = sm3;
    float* af   = sm3 + 16384;

    const int b  = blockIdx.y;
    const int n0 = blockIdx.x * 32;
    const int tid = threadIdx.x;

    for (int l = tid; l < 16384; l += 256) wo_s[l] = wo[l];
    for (int l = tid; l < 4096; l += 256) {
        int cc2 = l >> 5, nl = l & 31;
        af[nl*130 + cc2] = g_attn[(size_t)(b*CC + cc2)*NTOK + n0 + nl];
    }
    __syncthreads();

    const int lane = tid & 31;
    const int w = tid >> 5;
    const ull* arow = reinterpret_cast<const ull*>(af + lane*130);
    const ull* wou = reinterpret_cast<const ull*>(wo_s);

    ull acc[16];
#pragma unroll
    for (int k = 0; k < 16; ++k) acc[k] = 0ull;
    for (int cp = 0; cp < 64; ++cp) {
        ull av2 = arow[cp];
#pragma unroll
        for (int k = 0; k < 16; ++k)
            acc[k] = ffma2(wou[(w*16 + k)*64 + cp], av2, acc[k]);
    }
#pragma unroll
    for (int k = 0; k < 16; ++k) {
        float lo, hi; upk2(acc[k], lo, hi);
        float s = lo + hi;
        size_t idx = (size_t)(b*CC + w*16 + k)*NTOK + n0 + lane;
        out[idx] = x[idx] + s;
    }
}

// =================================================================
extern "C" void kernel_launch(void* const* d_in, const int* in_sizes, int n_in,
                              void* d_out, int out_size)
{
    const float* x    = (const float*)d_in[0];
    const float* wq   = (const float*)d_in[1];
    const float* wk   = (const float*)d_in[2];
    const float* wv   = (const float*)d_in[3];
    const float* dwq  = (const float*)d_in[4];
    const float* dwk  = (const float*)d_in[5];
    const float* dwv  = (const float*)d_in[6];
    const float* wo   = (const float*)d_in[7];
    const float* temp = (const float*)d_in[8];
    float* out = (float*)d_out;

    cudaFuncSetAttribute(attn_kernel, cudaFuncAttributeMaxDynamicSharedMemorySize, ATTN_SMEM_BYTES);
    cudaFuncSetAttribute(outconv_kernel, cudaFuncAttributeMaxDynamicSharedMemorySize, OC_SMEM_BYTES);

    qkv_kernel<<<dim3(BB*CC, 3), 256>>>(x, wq, wk, wv, dwq, dwk, dwv);
    attn_kernel<<<dim3(NTOK/16, BB*NHEADS), 512, ATTN_SMEM_BYTES>>>(temp);
    outconv_kernel<<<dim3(NTOK/32, BB), 256, OC_SMEM_BYTES>>>(x, wo, out);
}

// round 5
// speedup vs baseline: 1.6701x; 1.3816x over previous
#include <cuda_runtime.h>
#include <cuda_bf16.h>
#include <cuda_fp8.h>
#include <cstdint>

#define BB   2
#define CC   128
#define HH   48
#define NTOK 2304
#define NHEADS 8
#define CHH  16
#define KTOP 1843

typedef unsigned long long ull;

// ---------------- scratch ----------------
__device__ __nv_bfloat16 g_q16[BB*CC*NTOK];          // raw q bf16, [b*C+c][n]
__device__ __nv_bfloat16 g_kT[BB*NHEADS*NTOK*CHH];   // raw K bf16, [bh][n][ch]
__device__ __nv_bfloat16 g_v16[BB*CC*NTOK];          // raw v bf16
__device__ unsigned char g_v8[BB*CC*NTOK];           // v e4m3 (scaled)
__device__ float g_vsinv[BB*CC];                     // per-channel V inverse scale
__device__ float g_kinv[BB*NHEADS*CHH];              // per-(bh,ch) 1/||k||
__device__ float g_attn[BB*CC*NTOK];

// ---------------- f32x2 helpers ----------------
__device__ __forceinline__ void upk2(ull v, float& lo, float& hi) {
    asm("mov.b64 {%0, %1}, %2;" : "=f"(lo), "=f"(hi) : "l"(v));
}
__device__ __forceinline__ ull ffma2(ull a, ull b, ull c) {
    ull d; asm("fma.rn.f32x2 %0, %1, %2, %3;" : "=l"(d) : "l"(a), "l"(b), "l"(c)); return d;
}

// ---------------- fp8 helpers ----------------
__device__ __forceinline__ unsigned short pack2_e4m3(float lo, float hi) {
    unsigned short r;
    asm("cvt.rn.satfinite.e4m3x2.f32 %0, %1, %2;" : "=h"(r) : "f"(hi), "f"(lo));
    return r;
}
__device__ __forceinline__ void deq2_e4m3(unsigned short b2, float& lo, float& hi) {
    unsigned h2;
    asm("cvt.rn.f16x2.e4m3x2 %0, %1;" : "=r"(h2) : "h"(b2));
    __half2 hh = *reinterpret_cast<__half2*>(&h2);
    lo = __low2float(hh); hi = __high2float(hh);
}
__device__ __forceinline__ unsigned f2e4m3(float f) {
    return (unsigned)__nv_cvt_float_to_fp8(f, __NV_SATFINITE, __NV_E4M3);
}
__device__ __forceinline__ float e4m32f(unsigned b) {
    __half_raw hr = __nv_cvt_fp8_to_halfraw((__nv_fp8_storage_t)b, __NV_E4M3);
    return __half2float(*reinterpret_cast<__half*>(&hr));
}
__device__ __forceinline__ unsigned keymap4(unsigned u) {
    unsigned m = u & 0x80808080u;
    unsigned X = 0x80808080u | ((m >> 7) * 0x7Fu);
    return u ^ X;
}
__device__ __forceinline__ unsigned kinv8(unsigned k) {
    return (k & 0x80u) ? (k ^ 0x80u) : ((~k) & 0xFFu);
}

// ---------------- mma wrappers ----------------
__device__ __forceinline__ void mma_bf16(float& c0, float& c1, float& c2, float& c3,
                                         unsigned a0, unsigned a1, unsigned a2, unsigned a3,
                                         unsigned b0, unsigned b1) {
    asm volatile("mma.sync.aligned.m16n8k16.row.col.f32.bf16.bf16.f32 "
                 "{%0,%1,%2,%3}, {%4,%5,%6,%7}, {%8,%9}, {%0,%1,%2,%3};"
                 : "+f"(c0), "+f"(c1), "+f"(c2), "+f"(c3)
                 : "r"(a0), "r"(a1), "r"(a2), "r"(a3), "r"(b0), "r"(b1));
}
__device__ __forceinline__ void mma_e4m3(float& c0, float& c1, float& c2, float& c3,
                                         unsigned a0, unsigned a1, unsigned a2, unsigned a3,
                                         unsigned b0, unsigned b1) {
    asm volatile("mma.sync.aligned.m16n8k32.row.col.f32.e4m3.e4m3.f32 "
                 "{%0,%1,%2,%3}, {%4,%5,%6,%7}, {%8,%9}, {%0,%1,%2,%3};"
                 : "+f"(c0), "+f"(c1), "+f"(c2), "+f"(c3)
                 : "r"(a0), "r"(a1), "r"(a2), "r"(a3), "r"(b0), "r"(b1));
}

// ---------------- register 16-bin counting helpers ----------------
__device__ __forceinline__ void cadd(unsigned b, unsigned& c0, unsigned& c1,
                                     unsigned& c2, unsigned& c3) {
    unsigned val = 1u << ((b & 3u) << 3);
    if (b < 4u) c0 += val; else if (b < 8u) c1 += val;
    else if (b < 12u) c2 += val; else c3 += val;
}
__device__ __forceinline__ void red16(unsigned c0, unsigned c1, unsigned c2, unsigned c3,
                                      unsigned e[8]) {
    e[0] = c0 & 0x00FF00FFu; e[1] = (c0 >> 8) & 0x00FF00FFu;
    e[2] = c1 & 0x00FF00FFu; e[3] = (c1 >> 8) & 0x00FF00FFu;
    e[4] = c2 & 0x00FF00FFu; e[5] = (c2 >> 8) & 0x00FF00FFu;
    e[6] = c3 & 0x00FF00FFu; e[7] = (c3 >> 8) & 0x00FF00FFu;
#pragma unroll
    for (int off = 16; off; off >>= 1) {
#pragma unroll
        for (int j = 0; j < 8; ++j) e[j] += __shfl_xor_sync(0xffffffffu, e[j], off);
    }
}
__device__ __forceinline__ int pick16(const unsigned e[8], int& kk) {
    int h[16];
#pragma unroll
    for (int i = 0; i < 4; ++i)
#pragma unroll
        for (int j = 0; j < 4; ++j)
            h[4*i+j] = (int)((e[2*i + (j&1)] >> (16*(j>>1))) & 0xffffu);
    int cum = 0, d = 0, kkr = kk;
#pragma unroll
    for (int i = 15; i >= 0; --i) {
        int ncum = cum + h[i];
        if (cum < kk && ncum >= kk) { d = i; kkr = kk - cum; }
        cum = ncum;
    }
    kk = kkr;
    return d;
}

// =================================================================
// Kernel 1: qkv convs, 4 output channels per block (shared x reads).
// grid = (64 = b*32+cq, 3 types), 256 threads. No reductions here.
// =================================================================
__global__ __launch_bounds__(256) void qkv_kernel(
    const float* __restrict__ x,
    const float* __restrict__ wq, const float* __restrict__ wk, const float* __restrict__ wv,
    const float* __restrict__ dwq, const float* __restrict__ dwk, const float* __restrict__ dwv)
{
    __shared__ float sp[4][NTOK + 8];
    __shared__ float wp[4][32];
    __shared__ float wd[4][9];

    const int t  = blockIdx.y;
    const int b  = blockIdx.x >> 5;
    const int cq = blockIdx.x & 31;
    const int c0 = cq * 4;
    const int g  = c0 >> 5;
    const int tid = threadIdx.x;

    const float* wsel = (t == 0) ? wq : (t == 1) ? wk : wv;
    const float* dsel = (t == 0) ? dwq : (t == 1) ? dwk : dwv;

    if (tid < 128) wp[tid >> 5][tid & 31] = wsel[(c0 + (tid >> 5))*32 + (tid & 31)];
    if (tid < 36)  wd[tid / 9][tid % 9]   = dsel[(c0 + tid/9)*9 + tid % 9];
    __syncthreads();

    // pointwise grouped conv: 4 out-channels share x loads
    const float* xb = x + (size_t)(b*CC + g*32) * NTOK + tid;
    float a[4][9];
#pragma unroll
    for (int oc = 0; oc < 4; ++oc)
#pragma unroll
        for (int p = 0; p < 9; ++p) a[oc][p] = 0.f;

    for (int i = 0; i < 32; i += 2) {
        float x0[9], x1[9];
        const float* xi0 = xb + (size_t)i*NTOK;
        const float* xi1 = xb + (size_t)(i+1)*NTOK;
#pragma unroll
        for (int p = 0; p < 9; ++p) { x0[p] = xi0[p*256]; x1[p] = xi1[p*256]; }
#pragma unroll
        for (int oc = 0; oc < 4; ++oc) {
            const float w0 = wp[oc][i], w1 = wp[oc][i+1];
#pragma unroll
            for (int p = 0; p < 9; ++p) a[oc][p] += w0*x0[p] + w1*x1[p];
        }
    }
#pragma unroll
    for (int oc = 0; oc < 4; ++oc)
#pragma unroll
        for (int p = 0; p < 9; ++p) sp[oc][tid + p*256] = a[oc][p];
    __syncthreads();

    // depthwise 3x3 SAME, 4 channels; raw bf16 writeout
    for (int p = 0; p < 9; ++p) {
        int n = tid + p*256;
        int r = n / HH;
        int col = n - r*HH;
        float s[4] = {0.f, 0.f, 0.f, 0.f};
#pragma unroll
        for (int dy = 0; dy < 3; ++dy) {
            int rr = r + dy - 1;
            if ((unsigned)rr < (unsigned)HH) {
#pragma unroll
                for (int dx = 0; dx < 3; ++dx) {
                    int cc2 = col + dx - 1;
                    if ((unsigned)cc2 < (unsigned)HH) {
                        int nn = rr*HH + cc2;
                        int ki = dy*3 + dx;
#pragma unroll
                        for (int oc = 0; oc < 4; ++oc) s[oc] += wd[oc][ki] * sp[oc][nn];
                    }
                }
            }
        }
        if (t == 0) {
#pragma unroll
            for (int oc = 0; oc < 4; ++oc)
                g_q16[(size_t)(b*CC + c0 + oc)*NTOK + n] = __float2bfloat16(s[oc]);
        } else if (t == 1) {
            const int bh = b*NHEADS + (c0 >> 4);
            const int chb = c0 & 15;
            __nv_bfloat16* kT = g_kT + (size_t)bh*NTOK*CHH + (size_t)n*CHH + chb;
#pragma unroll
            for (int oc = 0; oc < 4; ++oc) kT[oc] = __float2bfloat16(s[oc]);
        } else {
#pragma unroll
            for (int oc = 0; oc < 4; ++oc)
                g_v16[(size_t)(b*CC + c0 + oc)*NTOK + n] = __float2bfloat16(s[oc]);
        }
    }
}

// =================================================================
// Kernel 1b: per-(bh,ch) K inverse norms. grid = 16 blocks.
// =================================================================
__global__ __launch_bounds__(256) void knorm_kernel()
{
    __shared__ float rs[512];
    const int bh = blockIdx.x;
    const int tid = threadIdx.x;
    const unsigned* kw = (const unsigned*)(g_kT + (size_t)bh*NTOK*CHH);
    const int cp = tid & 7;
    float s0 = 0.f, s1 = 0.f;
    for (int n = tid >> 3; n < NTOK; n += 32) {
        unsigned u = kw[n*8 + cp];
        float f0 = __uint_as_float(u << 16);
        float f1 = __uint_as_float(u & 0xffff0000u);
        s0 += f0*f0; s1 += f1*f1;
    }
    rs[tid*2] = s0; rs[tid*2 + 1] = s1;
    __syncthreads();
    for (int off = 128; off >= 8; off >>= 1) {
        if (tid < off) { rs[tid*2] += rs[(tid+off)*2]; rs[tid*2+1] += rs[(tid+off)*2+1]; }
        __syncthreads();
    }
    if (tid < 8) {
        g_kinv[bh*16 + 2*tid]     = 1.f / fmaxf(sqrtf(rs[tid*2]),   1e-12f);
        g_kinv[bh*16 + 2*tid + 1] = 1.f / fmaxf(sqrtf(rs[tid*2+1]), 1e-12f);
    }
}

// =================================================================
// Kernel 1c: per-(b,c) V max-scale + fp8 convert. grid = 256 blocks.
// =================================================================
__global__ __launch_bounds__(256) void vprep_kernel()
{
    __shared__ float rs[256];
    const int bc = blockIdx.x;
    const int tid = threadIdx.x;
    const __nv_bfloat16* vp = g_v16 + (size_t)bc * NTOK;
    float v[9];
    float m = 0.f;
#pragma unroll
    for (int p = 0; p < 9; ++p) {
        v[p] = __bfloat162float(vp[tid + p*256]);
        m = fmaxf(m, fabsf(v[p]));
    }
    rs[tid] = m;
    __syncthreads();
    for (int off = 128; off; off >>= 1) {
        if (tid < off) rs[tid] = fmaxf(rs[tid], rs[tid+off]);
        __syncthreads();
    }
    const float mx = rs[0];
    const float sc = (mx > 0.f) ? 240.f / mx : 0.f;
    if (tid == 0) g_vsinv[bc] = (mx > 0.f) ? mx / 240.f : 0.f;
    unsigned char* v8 = g_v8 + (size_t)bc * NTOK;
#pragma unroll
    for (int p = 0; p < 9; ++p)
        v8[tid + p*256] = (unsigned char)f2e4m3(v[p] * sc);
}

// =================================================================
// Kernel 2: fused attention. fp8 scores, single-pass nibble select.
// grid = (144, 16), 512 threads (16 warps; warp w owns query row w)
// =================================================================
#define SROWB 2320
#define ATTN_SM_S   (16*SROWB)
#define ATTN_SM_QA  512
#define ATTN_SM_SCR (16*256*4)
#define ATTN_SM_RST 64
#define ATTN_SMEM_BYTES (ATTN_SM_S + ATTN_SM_QA + ATTN_SM_SCR + ATTN_SM_RST)

__global__ __launch_bounds__(512, 2) void attn_kernel(const float* __restrict__ temperature)
{
    extern __shared__ unsigned char smraw[];
    unsigned char* smS = smraw;
    __nv_bfloat16* qA  = (__nv_bfloat16*)(smraw + ATTN_SM_S);
    float* scratch     = (float*)(smraw + ATTN_SM_S + ATTN_SM_QA);
    float* invz        = (float*)(smraw + ATTN_SM_S + ATTN_SM_QA + ATTN_SM_SCR);

    const int rt = blockIdx.x, bh = blockIdx.y;
    const int b = bh >> 3, h = bh & 7;
    const int bc0 = b*CC + h*CHH;
    const int row0 = rt * 16;
    const int tid = threadIdx.x;
    const int w = tid >> 5, lane = tid & 31;
    const float ts = temperature[h];

    // ---- phase 0: Q rows, L2-normalize over C_h, fold temp + K-norm ----
    if (tid < 256) {
        int r = tid >> 4, c = tid & 15;
        float qv = __bfloat162float(g_q16[(size_t)(bc0 + c)*NTOK + row0 + r]);
        float ss = qv * qv;
#pragma unroll
        for (int off = 8; off; off >>= 1) ss += __shfl_xor_sync(0xffffffffu, ss, off, 16);
        float qt = qv * ts * g_kinv[bh*16 + c] / fmaxf(sqrtf(ss), 1e-12f);
        qA[r*16 + c] = __float2bfloat16(qt);
    }
    __syncthreads();

    // ---- phase 1: scores via bf16 mma -> e4m3 smem, batched K loads ----
    {
        const unsigned* qAu = (const unsigned*)qA;
        int r = lane >> 2, kx = (lane & 3) * 2;
        unsigned a0 = qAu[(r*16 + kx) >> 1];
        unsigned a1 = qAu[((r+8)*16 + kx) >> 1];
        unsigned a2 = qAu[(r*16 + kx + 8) >> 1];
        unsigned a3 = qAu[((r+8)*16 + kx + 8) >> 1];

        const unsigned* kTu = (const unsigned*)(g_kT + (size_t)bh * NTOK * CHH);
        const int jl = lane >> 2, ko = lane & 3;
        const int cst = (lane & 3) * 2;
#pragma unroll
        for (int mb = 0; mb < 3; ++mb) {
            unsigned rb0[6], rb1[6];
#pragma unroll
            for (int m = 0; m < 6; ++m) {
                int j0 = w*144 + (mb*6 + m)*8;
                const unsigned* kp = kTu + (size_t)(j0 + jl)*8 + ko;
                rb0[m] = kp[0];
                rb1[m] = kp[4];
            }
#pragma unroll
            for (int m = 0; m < 6; ++m) {
                int j0 = w*144 + (mb*6 + m)*8;
                float c0 = 0.f, c1 = 0.f, c2 = 0.f, c3 = 0.f;
                mma_bf16(c0, c1, c2, c3, a0, a1, a2, a3, rb0[m], rb1[m]);
                int off = j0 + cst;
                *(unsigned short*)(smS + r*SROWB + off)     = pack2_e4m3(c0, c1);
                *(unsigned short*)(smS + (r+8)*SROWB + off) = pack2_e4m3(c2, c3);
            }
        }
    }
    __syncthreads();

    // ---- phase 2: single-pass nibble-radix select (no atomics) ----
    unsigned* srowU = (unsigned*)(smS + (size_t)w * SROWB);
    unsigned c0 = 0, c1 = 0, c2 = 0, c3 = 0, maxk = 0;
#pragma unroll 6
    for (int it = 0; it < 18; ++it) {
        unsigned k4 = keymap4(srowU[lane + it*32]);
        maxk = __vmaxu4(maxk, k4);
#pragma unroll
        for (int i = 0; i < 4; ++i)
            cadd((k4 >> (8*i + 4)) & 0xFu, c0, c1, c2, c3);
    }
#pragma unroll
    for (int off = 16; off; off >>= 1)
        maxk = __vmaxu4(maxk, __shfl_xor_sync(0xffffffffu, maxk, off));
    {
        unsigned mb = maxk;
        mb = (mb > (mb >> 16)) ? mb : (mb >> 16);
        unsigned lo8 = mb & 0xFFu, hi8 = (mb >> 8) & 0xFFu;
        maxk = (lo8 > hi8) ? lo8 : hi8;
    }
    const float rmax = e4m32f(kinv8(maxk));

    unsigned e[8];
    red16(c0, c1, c2, c3, e);
    int kk = KTOP;
    const unsigned d1 = (unsigned)pick16(e, kk);
    const unsigned tk = d1 << 4;     // nibble-granular threshold; whole bin included

    // ---- phase 3: masked softmax -> e4m3 weights in place ----
    float z = 0.f;
#pragma unroll 4
    for (int it = 0; it < 18; ++it) {
        unsigned u = srowU[lane + it*32];
        unsigned k4 = keymap4(u);
        float f0, f1, f2, f3;
        deq2_e4m3((unsigned short)(u & 0xffffu), f0, f1);
        deq2_e4m3((unsigned short)(u >> 16), f2, f3);
        float w0 = (((k4      ) & 0xFFu) >= tk) ? __expf(f0 - rmax) : 0.f;
        float w1 = (((k4 >>  8) & 0xFFu) >= tk) ? __expf(f1 - rmax) : 0.f;
        float w2 = (((k4 >> 16) & 0xFFu) >= tk) ? __expf(f2 - rmax) : 0.f;
        float w3 = (((k4 >> 24) & 0xFFu) >= tk) ? __expf(f3 - rmax) : 0.f;
        z += (w0 + w1) + (w2 + w3);
        unsigned s0 = (unsigned)pack2_e4m3(w0, w1);
        unsigned s1 = (unsigned)pack2_e4m3(w2, w3);
        srowU[lane + it*32] = s0 | (s1 << 16);
    }
#pragma unroll
    for (int off = 16; off; off >>= 1) z += __shfl_xor_sync(0xffffffffu, z, off);
    if (lane == 0) invz[w] = 1.f / z;
    __syncthreads();

    // ---- phase 4: PV via fp8 mma, warp strides 512-token chunks ----
    float acc[8];
#pragma unroll
    for (int i = 0; i < 8; ++i) acc[i] = 0.f;
    {
        const unsigned char* vb = g_v8 + (size_t)bc0 * NTOK;
        const int r = lane >> 2, kx = (lane & 3) * 4;
        const int nn = lane >> 2;
        for (int k0 = w*32; k0 < NTOK; k0 += 512) {
            unsigned A0 = *(const unsigned*)(smS + r*SROWB + k0 + kx);
            unsigned A1 = *(const unsigned*)(smS + (r+8)*SROWB + k0 + kx);
            unsigned A2 = *(const unsigned*)(smS + r*SROWB + k0 + kx + 16);
            unsigned A3 = *(const unsigned*)(smS + (r+8)*SROWB + k0 + kx + 16);
            unsigned B0 = *(const unsigned*)(vb + (size_t)nn*NTOK + k0 + kx);
            unsigned B1 = *(const unsigned*)(vb + (size_t)nn*NTOK + k0 + kx + 16);
            mma_e4m3(acc[0], acc[1], acc[2], acc[3], A0, A1, A2, A3, B0, B1);
            unsigned B2 = *(const unsigned*)(vb + (size_t)(nn+8)*NTOK + k0 + kx);
            unsigned B3 = *(const unsigned*)(vb + (size_t)(nn+8)*NTOK + k0 + kx + 16);
            mma_e4m3(acc[4], acc[5], acc[6], acc[7], A0, A1, A2, A3, B2, B3);
        }
    }
    {
        int r = lane >> 2, c2s = (lane & 3) * 2;
        float* sw = scratch + w*256;
        sw[r*16 + c2s]           = acc[0];
        sw[r*16 + c2s + 1]       = acc[1];
        sw[(r+8)*16 + c2s]       = acc[2];
        sw[(r+8)*16 + c2s + 1]   = acc[3];
        sw[r*16 + 8 + c2s]       = acc[4];
        sw[r*16 + 8 + c2s + 1]   = acc[5];
        sw[(r+8)*16 + 8 + c2s]   = acc[6];
        sw[(r+8)*16 + 8 + c2s+1] = acc[7];
    }
    __syncthreads();

    // ---- phase 5: cross-warp reduce, unscale, write ----
    if (tid < 256) {
        int r = tid >> 4, c = tid & 15;
        float s = 0.f;
#pragma unroll
        for (int wi = 0; wi < 16; ++wi) s += scratch[wi*256 + r*16 + c];
        g_attn[(size_t)(bc0 + c)*NTOK + row0 + r] = s * invz[r] * g_vsinv[bc0 + c];
    }
}

// =================================================================
// Kernel 3: out = x + wo @ attn  (1x1 conv + residual)
// =================================================================
#define OC_SMEM_FLOATS (16384 + 32*130)
#define OC_SMEM_BYTES  (OC_SMEM_FLOATS * 4)

__global__ __launch_bounds__(256) void outconv_kernel(
    const float* __restrict__ x, const float* __restrict__ wo, float* __restrict__ out)
{
    extern __shared__ float sm3[];
    float* wo_s = sm3;
    float* af   = sm3 + 16384;

    const int b  = blockIdx.y;
    const int n0 = blockIdx.x * 32;
    const int tid = threadIdx.x;

    for (int l = tid; l < 16384; l += 256) wo_s[l] = wo[l];
    for (int l = tid; l < 4096; l += 256) {
        int cc2 = l >> 5, nl = l & 31;
        af[nl*130 + cc2] = g_attn[(size_t)(b*CC + cc2)*NTOK + n0 + nl];
    }
    __syncthreads();

    const int lane = tid & 31;
    const int w = tid >> 5;
    const ull* arow = reinterpret_cast<const ull*>(af + lane*130);
    const ull* wou = reinterpret_cast<const ull*>(wo_s);

    ull acc[16];
#pragma unroll
    for (int k = 0; k < 16; ++k) acc[k] = 0ull;
    for (int cp = 0; cp < 64; ++cp) {
        ull av2 = arow[cp];
#pragma unroll
        for (int k = 0; k < 16; ++k)
            acc[k] = ffma2(wou[(w*16 + k)*64 + cp], av2, acc[k]);
    }
#pragma unroll
    for (int k = 0; k < 16; ++k) {
        float lo, hi; upk2(acc[k], lo, hi);
        float s = lo + hi;
        size_t idx = (size_t)(b*CC + w*16 + k)*NTOK + n0 + lane;
        out[idx] = x[idx] + s;
    }
}

// =================================================================
extern "C" void kernel_launch(void* const* d_in, const int* in_sizes, int n_in,
                              void* d_out, int out_size)
{
    const float* x    = (const float*)d_in[0];
    const float* wq   = (const float*)d_in[1];
    const float* wk   = (const float*)d_in[2];
    const float* wv   = (const float*)d_in[3];
    const float* dwq  = (const float*)d_in[4];
    const float* dwk  = (const float*)d_in[5];
    const float* dwv  = (const float*)d_in[6];
    const float* wo   = (const float*)d_in[7];
    const float* temp = (const float*)d_in[8];
    float* out = (float*)d_out;

    cudaFuncSetAttribute(attn_kernel, cudaFuncAttributeMaxDynamicSharedMemorySize, ATTN_SMEM_BYTES);
    cudaFuncSetAttribute(outconv_kernel, cudaFuncAttributeMaxDynamicSharedMemorySize, OC_SMEM_BYTES);

    qkv_kernel<<<dim3(64, 3), 256>>>(x, wq, wk, wv, dwq, dwk, dwv);
    knorm_kernel<<<16, 256>>>();
    vprep_kernel<<<256, 256>>>();
    attn_kernel<<<dim3(NTOK/16, BB*NHEADS), 512, ATTN_SMEM_BYTES>>>(temp);
    outconv_kernel<<<dim3(NTOK/32, BB), 256, OC_SMEM_BYTES>>>(x, wo, out);
}

// round 6
// speedup vs baseline: 2.4229x; 1.4508x over previous
#include <cuda_runtime.h>
#include <cuda_bf16.h>
#include <cuda_fp16.h>
#include <cuda_fp8.h>
#include <cstdint>

#define BB   2
#define CC   128
#define HH   48
#define NTOK 2304
#define NHEADS 8
#define CHH  16
#define KTOP 1843

typedef unsigned long long ull;

// ---------------- scratch ----------------
__device__ __nv_bfloat16 g_q16[BB*CC*NTOK];          // raw q bf16, [b*C+c][n]
__device__ __nv_bfloat16 g_kT[BB*NHEADS*NTOK*CHH];   // raw K bf16, [bh][n][ch]
__device__ __nv_bfloat16 g_v16[BB*CC*NTOK];          // raw v bf16
__device__ unsigned char g_v8[BB*CC*NTOK];           // v e4m3 (scaled)
__device__ float g_vsinv[BB*CC];                     // per-channel V inverse scale
__device__ float g_kinv[BB*NHEADS*CHH];              // per-(bh,ch) 1/||k||
__device__ float g_attn[BB*CC*NTOK];

// ---------------- f32x2 helpers ----------------
__device__ __forceinline__ void upk2(ull v, float& lo, float& hi) {
    asm("mov.b64 {%0, %1}, %2;" : "=f"(lo), "=f"(hi) : "l"(v));
}
__device__ __forceinline__ ull ffma2(ull a, ull b, ull c) {
    ull d; asm("fma.rn.f32x2 %0, %1, %2, %3;" : "=l"(d) : "l"(a), "l"(b), "l"(c)); return d;
}

// ---------------- fp8 helpers ----------------
__device__ __forceinline__ unsigned short pack2_e4m3(float lo, float hi) {
    unsigned short r;
    asm("cvt.rn.satfinite.e4m3x2.f32 %0, %1, %2;" : "=h"(r) : "f"(hi), "f"(lo));
    return r;
}
__device__ __forceinline__ unsigned f2e4m3(float f) {
    return (unsigned)__nv_cvt_float_to_fp8(f, __NV_SATFINITE, __NV_E4M3);
}
// monotone byte keymap over 4 packed e4m3 (forward)
__device__ __forceinline__ unsigned keymap4(unsigned u) {
    unsigned m = u & 0x80808080u;
    unsigned X = 0x80808080u | ((m >> 7) * 0x7Fu);
    return u ^ X;
}

// ---------------- mma wrappers ----------------
__device__ __forceinline__ void mma_bf16(float& c0, float& c1, float& c2, float& c3,
                                         unsigned a0, unsigned a1, unsigned a2, unsigned a3,
                                         unsigned b0, unsigned b1) {
    asm volatile("mma.sync.aligned.m16n8k16.row.col.f32.bf16.bf16.f32 "
                 "{%0,%1,%2,%3}, {%4,%5,%6,%7}, {%8,%9}, {%0,%1,%2,%3};"
                 : "+f"(c0), "+f"(c1), "+f"(c2), "+f"(c3)
                 : "r"(a0), "r"(a1), "r"(a2), "r"(a3), "r"(b0), "r"(b1));
}
__device__ __forceinline__ void mma_e4m3(float& c0, float& c1, float& c2, float& c3,
                                         unsigned a0, unsigned a1, unsigned a2, unsigned a3,
                                         unsigned b0, unsigned b1) {
    asm volatile("mma.sync.aligned.m16n8k32.row.col.f32.e4m3.e4m3.f32 "
                 "{%0,%1,%2,%3}, {%4,%5,%6,%7}, {%8,%9}, {%0,%1,%2,%3};"
                 : "+f"(c0), "+f"(c1), "+f"(c2), "+f"(c3)
                 : "r"(a0), "r"(a1), "r"(a2), "r"(a3), "r"(b0), "r"(b1));
}

// =================================================================
// Kernel 1: qkv convs, 4 output channels per block (shared x reads).
// =================================================================
__global__ __launch_bounds__(256) void qkv_kernel(
    const float* __restrict__ x,
    const float* __restrict__ wq, const float* __restrict__ wk, const float* __restrict__ wv,
    const float* __restrict__ dwq, const float* __restrict__ dwk, const float* __restrict__ dwv)
{
    __shared__ float sp[4][NTOK + 8];
    __shared__ float wp[4][32];
    __shared__ float wd[4][9];

    const int t  = blockIdx.y;
    const int b  = blockIdx.x >> 5;
    const int cq = blockIdx.x & 31;
    const int c0 = cq * 4;
    const int g  = c0 >> 5;
    const int tid = threadIdx.x;

    const float* wsel = (t == 0) ? wq : (t == 1) ? wk : wv;
    const float* dsel = (t == 0) ? dwq : (t == 1) ? dwk : dwv;

    if (tid < 128) wp[tid >> 5][tid & 31] = wsel[(c0 + (tid >> 5))*32 + (tid & 31)];
    if (tid < 36)  wd[tid / 9][tid % 9]   = dsel[(c0 + tid/9)*9 + tid % 9];
    __syncthreads();

    const float* xb = x + (size_t)(b*CC + g*32) * NTOK + tid;
    float a[4][9];
#pragma unroll
    for (int oc = 0; oc < 4; ++oc)
#pragma unroll
        for (int p = 0; p < 9; ++p) a[oc][p] = 0.f;

    for (int i = 0; i < 32; i += 2) {
        float x0[9], x1[9];
        const float* xi0 = xb + (size_t)i*NTOK;
        const float* xi1 = xb + (size_t)(i+1)*NTOK;
#pragma unroll
        for (int p = 0; p < 9; ++p) { x0[p] = xi0[p*256]; x1[p] = xi1[p*256]; }
#pragma unroll
        for (int oc = 0; oc < 4; ++oc) {
            const float w0 = wp[oc][i], w1 = wp[oc][i+1];
#pragma unroll
            for (int p = 0; p < 9; ++p) a[oc][p] += w0*x0[p] + w1*x1[p];
        }
    }
#pragma unroll
    for (int oc = 0; oc < 4; ++oc)
#pragma unroll
        for (int p = 0; p < 9; ++p) sp[oc][tid + p*256] = a[oc][p];
    __syncthreads();

    for (int p = 0; p < 9; ++p) {
        int n = tid + p*256;
        int r = n / HH;
        int col = n - r*HH;
        float s[4] = {0.f, 0.f, 0.f, 0.f};
#pragma unroll
        for (int dy = 0; dy < 3; ++dy) {
            int rr = r + dy - 1;
            if ((unsigned)rr < (unsigned)HH) {
#pragma unroll
                for (int dx = 0; dx < 3; ++dx) {
                    int cc2 = col + dx - 1;
                    if ((unsigned)cc2 < (unsigned)HH) {
                        int nn = rr*HH + cc2;
                        int ki = dy*3 + dx;
#pragma unroll
                        for (int oc = 0; oc < 4; ++oc) s[oc] += wd[oc][ki] * sp[oc][nn];
                    }
                }
            }
        }
        if (t == 0) {
#pragma unroll
            for (int oc = 0; oc < 4; ++oc)
                g_q16[(size_t)(b*CC + c0 + oc)*NTOK + n] = __float2bfloat16(s[oc]);
        } else if (t == 1) {
            const int bh = b*NHEADS + (c0 >> 4);
            const int chb = c0 & 15;
            __nv_bfloat16* kT = g_kT + (size_t)bh*NTOK*CHH + (size_t)n*CHH + chb;
#pragma unroll
            for (int oc = 0; oc < 4; ++oc) kT[oc] = __float2bfloat16(s[oc]);
        } else {
#pragma unroll
            for (int oc = 0; oc < 4; ++oc)
                g_v16[(size_t)(b*CC + c0 + oc)*NTOK + n] = __float2bfloat16(s[oc]);
        }
    }
}

// =================================================================
// Kernel 1b: per-(bh,ch) K inverse norms. grid = 16 blocks.
// =================================================================
__global__ __launch_bounds__(256) void knorm_kernel()
{
    __shared__ float rs[512];
    const int bh = blockIdx.x;
    const int tid = threadIdx.x;
    const unsigned* kw = (const unsigned*)(g_kT + (size_t)bh*NTOK*CHH);
    const int cp = tid & 7;
    float s0 = 0.f, s1 = 0.f;
    for (int n = tid >> 3; n < NTOK; n += 32) {
        unsigned u = kw[n*8 + cp];
        float f0 = __uint_as_float(u << 16);
        float f1 = __uint_as_float(u & 0xffff0000u);
        s0 += f0*f0; s1 += f1*f1;
    }
    rs[tid*2] = s0; rs[tid*2 + 1] = s1;
    __syncthreads();
    for (int off = 128; off >= 8; off >>= 1) {
        if (tid < off) { rs[tid*2] += rs[(tid+off)*2]; rs[tid*2+1] += rs[(tid+off)*2+1]; }
        __syncthreads();
    }
    if (tid < 8) {
        g_kinv[bh*16 + 2*tid]     = 1.f / fmaxf(sqrtf(rs[tid*2]),   1e-12f);
        g_kinv[bh*16 + 2*tid + 1] = 1.f / fmaxf(sqrtf(rs[tid*2+1]), 1e-12f);
    }
}

// =================================================================
// Kernel 1c: per-(b,c) V max-scale + fp8 convert. grid = 256 blocks.
// =================================================================
__global__ __launch_bounds__(256) void vprep_kernel()
{
    __shared__ float rs[256];
    const int bc = blockIdx.x;
    const int tid = threadIdx.x;
    const __nv_bfloat16* vp = g_v16 + (size_t)bc * NTOK;
    float v[9];
    float m = 0.f;
#pragma unroll
    for (int p = 0; p < 9; ++p) {
        v[p] = __bfloat162float(vp[tid + p*256]);
        m = fmaxf(m, fabsf(v[p]));
    }
    rs[tid] = m;
    __syncthreads();
    for (int off = 128; off; off >>= 1) {
        if (tid < off) rs[tid] = fmaxf(rs[tid], rs[tid+off]);
        __syncthreads();
    }
    const float mx = rs[0];
    const float sc = (mx > 0.f) ? 240.f / mx : 0.f;
    if (tid == 0) g_vsinv[bc] = (mx > 0.f) ? mx / 240.f : 0.f;
    unsigned char* v8 = g_v8 + (size_t)bc * NTOK;
#pragma unroll
    for (int p = 0; p < 9; ++p)
        v8[tid + p*256] = (unsigned char)f2e4m3(v[p] * sc);
}

// =================================================================
// Kernel 2: fused attention.
//  phase 1: bf16 mma -> keymapped e4m3 scores in smem
//  phase 2: 4-pass vset/dp4a binary search -> nibble threshold
//  phase 3: f16x2 exp (no row max; shift by |ts|) -> masked e4m3 weights
//  phase 4: fp8 PV mma + ones-column mma for Z
// grid = (144, 16), 512 threads (16 warps; warp w owns query row w)
// =================================================================
#define SROWB 2320
#define ATTN_SM_S   (16*SROWB)
#define ATTN_SM_QA  512
#define ATTN_SM_SCR (16*256*4)
#define ATTN_SM_ZS  (16*16*4)
#define ATTN_SMEM_BYTES (ATTN_SM_S + ATTN_SM_QA + ATTN_SM_SCR + ATTN_SM_ZS)

__global__ __launch_bounds__(512, 2) void attn_kernel(const float* __restrict__ temperature)
{
    extern __shared__ unsigned char smraw[];
    unsigned char* smS = smraw;
    __nv_bfloat16* qA  = (__nv_bfloat16*)(smraw + ATTN_SM_S);
    float* scratch     = (float*)(smraw + ATTN_SM_S + ATTN_SM_QA);
    float* zs          = (float*)(smraw + ATTN_SM_S + ATTN_SM_QA + ATTN_SM_SCR);

    const int rt = blockIdx.x, bh = blockIdx.y;
    const int b = bh >> 3, h = bh & 7;
    const int bc0 = b*CC + h*CHH;
    const int row0 = rt * 16;
    const int tid = threadIdx.x;
    const int w = tid >> 5, lane = tid & 31;
    const float ts = temperature[h];

    // ---- phase 0: Q rows, L2-normalize over C_h, fold temp + K-norm ----
    if (tid < 256) {
        int r = tid >> 4, c = tid & 15;
        float qv = __bfloat162float(g_q16[(size_t)(bc0 + c)*NTOK + row0 + r]);
        float ss = qv * qv;
#pragma unroll
        for (int off = 8; off; off >>= 1) ss += __shfl_xor_sync(0xffffffffu, ss, off, 16);
        float qt = qv * ts * g_kinv[bh*16 + c] / fmaxf(sqrtf(ss), 1e-12f);
        qA[r*16 + c] = __float2bfloat16(qt);
    }
    __syncthreads();

    // ---- phase 1: scores via bf16 mma -> keymapped e4m3 smem ----
    {
        const unsigned* qAu = (const unsigned*)qA;
        int r = lane >> 2, kx = (lane & 3) * 2;
        unsigned a0 = qAu[(r*16 + kx) >> 1];
        unsigned a1 = qAu[((r+8)*16 + kx) >> 1];
        unsigned a2 = qAu[(r*16 + kx + 8) >> 1];
        unsigned a3 = qAu[((r+8)*16 + kx + 8) >> 1];

        const unsigned* kTu = (const unsigned*)(g_kT + (size_t)bh * NTOK * CHH);
        const int jl = lane >> 2, ko = lane & 3;
        const int cst = (lane & 3) * 2;
#pragma unroll
        for (int mb = 0; mb < 3; ++mb) {
            unsigned rb0[6], rb1[6];
#pragma unroll
            for (int m = 0; m < 6; ++m) {
                int j0 = w*144 + (mb*6 + m)*8;
                const unsigned* kp = kTu + (size_t)(j0 + jl)*8 + ko;
                rb0[m] = kp[0];
                rb1[m] = kp[4];
            }
#pragma unroll
            for (int m = 0; m < 6; ++m) {
                int j0 = w*144 + (mb*6 + m)*8;
                float c0 = 0.f, c1 = 0.f, c2 = 0.f, c3 = 0.f;
                mma_bf16(c0, c1, c2, c3, a0, a1, a2, a3, rb0[m], rb1[m]);
                int off = j0 + cst;
                unsigned comb = (unsigned)pack2_e4m3(c0, c1)
                              | ((unsigned)pack2_e4m3(c2, c3) << 16);
                comb = keymap4(comb);
                *(unsigned short*)(smS + r*SROWB + off)     = (unsigned short)comb;
                *(unsigned short*)(smS + (r+8)*SROWB + off) = (unsigned short)(comb >> 16);
            }
        }
    }
    __syncthreads();

    // ---- phase 2: nibble threshold via 4-pass binary search ----
    unsigned* srowU = (unsigned*)(smS + (size_t)w * SROWB);
    int lo = 0, hi = 15;
#pragma unroll
    for (int pass = 0; pass < 4; ++pass) {
        int mid = (lo + hi + 1) >> 1;
        unsigned t4 = (unsigned)(mid << 4) * 0x01010101u;
        int cnt = 0;
#pragma unroll 6
        for (int it = 0; it < 18; ++it) {
            unsigned u = srowU[lane + it*32];
            cnt = __dp4a((int)__vsetgeu4(u, t4), 0x01010101, cnt);
        }
#pragma unroll
        for (int off = 16; off; off >>= 1) cnt += __shfl_xor_sync(0xffffffffu, cnt, off);
        if (cnt >= KTOP) lo = mid; else hi = mid - 1;
    }
    const unsigned tk4 = ((unsigned)(lo << 4)) * 0x01010101u;

    // ---- phase 3: f16x2 softmax weights (shift by |ts|), masked, in place ----
    {
        const float l2ef = 1.4426950408889634f;
        const float shift = fabsf(ts);
        const __half2 hl2e = __float2half2_rn(l2ef);
        const __half2 hb   = __float2half2_rn(-shift * l2ef);
#pragma unroll 3
        for (int it = 0; it < 18; ++it) {
            unsigned k = srowU[lane + it*32];
            unsigned mff = __vsetgeu4(k, tk4) * 255u;
            // inverse keymap: positive(k&0x80): ^0x80 ; negative: ~k
            unsigned sb = (k & 0x80808080u) >> 7;
            unsigned u = (~k) ^ (sb * 0x7Fu);
            unsigned hlo, hhi;
            asm("cvt.rn.f16x2.e4m3x2 %0, %1;" : "=r"(hlo) : "h"((unsigned short)(u & 0xffffu)));
            asm("cvt.rn.f16x2.e4m3x2 %0, %1;" : "=r"(hhi) : "h"((unsigned short)(u >> 16)));
            __half2 alo = __hfma2(*(__half2*)&hlo, hl2e, hb);
            __half2 ahi = __hfma2(*(__half2*)&hhi, hl2e, hb);
            unsigned wlo, whi;
            asm("ex2.approx.f16x2 %0, %1;" : "=r"(wlo) : "r"(*(unsigned*)&alo));
            asm("ex2.approx.f16x2 %0, %1;" : "=r"(whi) : "r"(*(unsigned*)&ahi));
            unsigned short plo, phi;
            asm("cvt.rn.satfinite.e4m3x2.f16x2 %0, %1;" : "=h"(plo) : "r"(wlo));
            asm("cvt.rn.satfinite.e4m3x2.f16x2 %0, %1;" : "=h"(phi) : "r"(whi));
            srowU[lane + it*32] = ((unsigned)plo | ((unsigned)phi << 16)) & mff;
        }
    }
    __syncthreads();

    // ---- phase 4: PV via fp8 mma + ones-column mma for Z ----
    float acc[8];
#pragma unroll
    for (int i = 0; i < 8; ++i) acc[i] = 0.f;
    float za0 = 0.f, za1 = 0.f, za2 = 0.f, za3 = 0.f;
    {
        const unsigned char* vb = g_v8 + (size_t)bc0 * NTOK;
        const int r = lane >> 2, kx = (lane & 3) * 4;
        const int nn = lane >> 2;
        const unsigned bz = (lane < 4) ? 0x38383838u : 0u;   // e4m3 1.0 in col 0
        for (int k0 = w*32; k0 < NTOK; k0 += 512) {
            unsigned A0 = *(const unsigned*)(smS + r*SROWB + k0 + kx);
            unsigned A1 = *(const unsigned*)(smS + (r+8)*SROWB + k0 + kx);
            unsigned A2 = *(const unsigned*)(smS + r*SROWB + k0 + kx + 16);
            unsigned A3 = *(const unsigned*)(smS + (r+8)*SROWB + k0 + kx + 16);
            unsigned B0 = *(const unsigned*)(vb + (size_t)nn*NTOK + k0 + kx);
            unsigned B1 = *(const unsigned*)(vb + (size_t)nn*NTOK + k0 + kx + 16);
            mma_e4m3(acc[0], acc[1], acc[2], acc[3], A0, A1, A2, A3, B0, B1);
            unsigned B2 = *(const unsigned*)(vb + (size_t)(nn+8)*NTOK + k0 + kx);
            unsigned B3 = *(const unsigned*)(vb + (size_t)(nn+8)*NTOK + k0 + kx + 16);
            mma_e4m3(acc[4], acc[5], acc[6], acc[7], A0, A1, A2, A3, B2, B3);
            mma_e4m3(za0, za1, za2, za3, A0, A1, A2, A3, bz, bz);
        }
    }
    {
        int r = lane >> 2, c2s = (lane & 3) * 2;
        float* sw = scratch + w*256;
        sw[r*16 + c2s]           = acc[0];
        sw[r*16 + c2s + 1]       = acc[1];
        sw[(r+8)*16 + c2s]       = acc[2];
        sw[(r+8)*16 + c2s + 1]   = acc[3];
        sw[r*16 + 8 + c2s]       = acc[4];
        sw[r*16 + 8 + c2s + 1]   = acc[5];
        sw[(r+8)*16 + 8 + c2s]   = acc[6];
        sw[(r+8)*16 + 8 + c2s+1] = acc[7];
        if ((lane & 3) == 0) {
            zs[w*16 + r]     = za0;
            zs[w*16 + 8 + r] = za2;
        }
    }
    __syncthreads();

    // ---- phase 5: cross-warp reduce, z-normalize, unscale, write ----
    if (tid < 256) {
        int r = tid >> 4, c = tid & 15;
        float s = 0.f, zr = 0.f;
#pragma unroll
        for (int wi = 0; wi < 16; ++wi) {
            s  += scratch[wi*256 + r*16 + c];
            zr += zs[wi*16 + r];
        }
        g_attn[(size_t)(bc0 + c)*NTOK + row0 + r] = s / zr * g_vsinv[bc0 + c];
    }
}

// =================================================================
// Kernel 3: out = x + wo @ attn  (1x1 conv + residual)
// =================================================================
#define OC_SMEM_FLOATS (16384 + 32*130)
#define OC_SMEM_BYTES  (OC_SMEM_FLOATS * 4)

__global__ __launch_bounds__(256) void outconv_kernel(
    const float* __restrict__ x, const float* __restrict__ wo, float* __restrict__ out)
{
    extern __shared__ float sm3[];
    float* wo_s = sm3;
    float* af   = sm3 + 16384;

    const int b  = blockIdx.y;
    const int n0 = blockIdx.x * 32;
    const int tid = threadIdx.x;

    for (int l = tid; l < 16384; l += 256) wo_s[l] = wo[l];
    for (int l = tid; l < 4096; l += 256) {
        int cc2 = l >> 5, nl = l & 31;
        af[nl*130 + cc2] = g_attn[(size_t)(b*CC + cc2)*NTOK + n0 + nl];
    }
    __syncthreads();

    const int lane = tid & 31;
    const int w = tid >> 5;
    const ull* arow = reinterpret_cast<const ull*>(af + lane*130);
    const ull* wou = reinterpret_cast<const ull*>(wo_s);

    ull acc[16];
#pragma unroll
    for (int k = 0; k < 16; ++k) acc[k] = 0ull;
    for (int cp = 0; cp < 64; ++cp) {
        ull av2 = arow[cp];
#pragma unroll
        for (int k = 0; k < 16; ++k)
            acc[k] = ffma2(wou[(w*16 + k)*64 + cp], av2, acc[k]);
    }
#pragma unroll
    for (int k = 0; k < 16; ++k) {
        float lo, hi; upk2(acc[k], lo, hi);
        float s = lo + hi;
        size_t idx = (size_t)(b*CC + w*16 + k)*NTOK + n0 + lane;
        out[idx] = x[idx] + s;
    }
}

// =================================================================
extern "C" void kernel_launch(void* const* d_in, const int* in_sizes, int n_in,
                              void* d_out, int out_size)
{
    const float* x    = (const float*)d_in[0];
    const float* wq   = (const float*)d_in[1];
    const float* wk   = (const float*)d_in[2];
    const float* wv   = (const float*)d_in[3];
    const float* dwq  = (const float*)d_in[4];
    const float* dwk  = (const float*)d_in[5];
    const float* dwv  = (const float*)d_in[6];
    const float* wo   = (const float*)d_in[7];
    const float* temp = (const float*)d_in[8];
    float* out = (float*)d_out;

    cudaFuncSetAttribute(attn_kernel, cudaFuncAttributeMaxDynamicSharedMemorySize, ATTN_SMEM_BYTES);
    cudaFuncSetAttribute(outconv_kernel, cudaFuncAttributeMaxDynamicSharedMemorySize, OC_SMEM_BYTES);

    qkv_kernel<<<dim3(64, 3), 256>>>(x, wq, wk, wv, dwq, dwk, dwv);
    knorm_kernel<<<16, 256>>>();
    vprep_kernel<<<256, 256>>>();
    attn_kernel<<<dim3(NTOK/16, BB*NHEADS), 512, ATTN_SMEM_BYTES>>>(temp);
    outconv_kernel<<<dim3(NTOK/32, BB), 256, OC_SMEM_BYTES>>>(x, wo, out);
}